// round 6
// baseline (speedup 1.0000x reference)
#include <cuda_runtime.h>
#include <cuda_bf16.h>
#include <cstdint>

#define BATCH 32
#define CIN   512
#define COUT  2048
#define HEADS 8
#define DHEAD 256
#define NPIX  256
#define SPARSITY 7

// Scratch (tf32 bit patterns stored as unsigned)
__device__ unsigned g_xc [BATCH * CIN * NPIX];
__device__ unsigned g_wqc[COUT * CIN];
__device__ unsigned g_wkc[COUT * CIN];
__device__ unsigned g_wvc[COUT * CIN];
__device__ unsigned g_woc[COUT * COUT];

__device__ unsigned g_q    [BATCH * COUT * NPIX];  // [d][n] tf32 bits
__device__ unsigned g_k    [BATCH * COUT * NPIX];
__device__ unsigned g_v    [BATCH * COUT * NPIX];
__device__ unsigned g_ao   [BATCH * COUT * NPIX];  // [d][n] tf32 bits
__device__ float    g_attn [BATCH * HEADS * NPIX * NPIX];
__device__ unsigned g_sattn[BATCH * HEADS * NPIX * NPIX];

__device__ int   g_t7i[256 * SPARSITY];
__device__ float g_t7v[256 * SPARSITY];
__device__ int   g_csc_row[256 * 256];
__device__ float g_csc_val[256 * 256];
__device__ int   g_csc_cnt[256];

// ---------------------------------------------------------------------------
__device__ __forceinline__ unsigned f2tf(float x) {
    unsigned r;
    asm("cvt.rna.tf32.f32 %0, %1;" : "=r"(r) : "f"(x));
    return r;
}

__device__ __forceinline__ void mma_tf32(float c[4],
    unsigned a0, unsigned a1, unsigned a2, unsigned a3,
    unsigned b0, unsigned b1)
{
    asm volatile(
        "mma.sync.aligned.m16n8k8.row.col.f32.tf32.tf32.f32 "
        "{%0,%1,%2,%3}, {%4,%5,%6,%7}, {%8,%9}, {%0,%1,%2,%3};"
        : "+f"(c[0]), "+f"(c[1]), "+f"(c[2]), "+f"(c[3])
        : "r"(a0), "r"(a1), "r"(a2), "r"(a3), "r"(b0), "r"(b1));
}

__device__ __forceinline__ void cpa16(unsigned saddr, const void* gptr) {
    asm volatile("cp.async.cg.shared.global [%0], [%1], 16;\n"
                 :: "r"(saddr), "l"(gptr));
}
#define CP_COMMIT() asm volatile("cp.async.commit_group;\n")
#define CP_WAIT1()  asm volatile("cp.async.wait_group 1;\n")
#define CP_WAIT0()  asm volatile("cp.async.wait_group 0;\n")

__device__ __forceinline__ uint32_t smem_u32(const void* p) {
    uint32_t a;
    asm("{ .reg .u64 t; cvta.to.shared.u64 t, %1; cvt.u32.u64 %0, t; }"
        : "=r"(a) : "l"(p));
    return a;
}

// ---------------------------------------------------------------------------
__global__ void cvt_tf32(const float4* __restrict__ src, uint4* __restrict__ dst, int n4) {
    int i = blockIdx.x * blockDim.x + threadIdx.x;
    if (i < n4) {
        float4 v = src[i];
        uint4 u;
        u.x = f2tf(v.x); u.y = f2tf(v.y); u.z = f2tf(v.z); u.w = f2tf(v.w);
        dst[i] = u;
    }
}

// ---------------------------------------------------------------------------
__global__ void sparsify_topk(const float* __restrict__ coeff) {
    int r = blockIdx.x;
    int t = threadIdx.x;
    __shared__ float av[2048];
    __shared__ float rv[256];
    __shared__ int   ri[256];

    const float* row = coeff + (size_t)r * 2048;
    for (int j = t; j < 2048; j += 256) av[j] = fabsf(row[j]);
    __syncthreads();

    for (int it = 0; it < SPARSITY; it++) {
        float best = -1.0f; int bi = 1 << 30;
        for (int j = t; j < 2048; j += 256) {
            float v = av[j];
            if (v > best) { best = v; bi = j; }
        }
        rv[t] = best; ri[t] = bi;
        __syncthreads();
        for (int s = 128; s > 0; s >>= 1) {
            if (t < s) {
                if (rv[t + s] > rv[t] || (rv[t + s] == rv[t] && ri[t + s] < ri[t])) {
                    rv[t] = rv[t + s]; ri[t] = ri[t + s];
                }
            }
            __syncthreads();
        }
        if (t == 0) {
            int idx = ri[0];
            g_t7i[r * SPARSITY + it] = idx;
            g_t7v[r * SPARSITY + it] = row[idx];
            av[idx] = -2.0f;
        }
        __syncthreads();
    }
}

__global__ void build_csc() {
    int p = threadIdx.x;
    int cnt = 0;
    for (int r = 0; r < 256; r++) {
        #pragma unroll
        for (int j = 0; j < SPARSITY; j++) {
            if (g_t7i[r * SPARSITY + j] == p) {
                g_csc_row[p * 256 + cnt] = r;
                g_csc_val[p * 256 + cnt] = g_t7v[r * SPARSITY + j];
                cnt++;
            }
        }
    }
    g_csc_cnt[p] = cnt;
}

// ---------------------------------------------------------------------------
// GEMM scheme: block 256(M) x 128(N), BK=16, 256 thr = 8 warps (4m x 2n),
// warp tile 64x64 (4 m-frags x 8 n-frags), mma m16n8k8 tf32,
// 2-stage cp.async. Dynamic smem.
// wm = (wid>>1)*64, wn = (wid&1)*64, g = lane>>2, tig = lane&3.
// ---------------------------------------------------------------------------

// conv1x1: Y[b][m][n] = sum_k W[m][k]*X[b][k][n] + bias[m]
// A = W row-major [256][16] str 20 ; B = X k-major [16][128] str 136.
// grid (NPIX/128, COUT/256, BATCH) = (2, 8, 32)
__global__ __launch_bounds__(256) void conv_mma3(
    const unsigned* __restrict__ W, const float* __restrict__ bias,
    const unsigned* __restrict__ X, float* __restrict__ Y, int K, int round_out)
{
    extern __shared__ char smem[];
    const uint32_t sb = smem_u32(smem);
    unsigned* Asm = (unsigned*)smem;                    // 2 x 256*20
    unsigned* Bsm = (unsigned*)(smem + 40960);          // 2 x 16*136

    const int b  = blockIdx.z;
    const int m0 = blockIdx.y * 256;
    const int n0 = blockIdx.x * 128;
    const unsigned* Xb = X + (size_t)b * K * NPIX;
    float*          Yb = Y + (size_t)b * COUT * NPIX;

    const int t = threadIdx.x, lane = t & 31, wid = t >> 5;
    const int g = lane >> 2, tig = lane & 3;
    const int wm = (wid >> 1) * 64, wn = (wid & 1) * 64;

    const int NT = K >> 4;

    // prologue stage 0
    {
        #pragma unroll
        for (int i = 0; i < 4; i++) {               // A: 1024 chunks
            int c = t + 256 * i;
            int row = c >> 2, col = (c & 3) * 4;
            cpa16(sb + (unsigned)(row * 20 + col) * 4u,
                  W + (size_t)(m0 + row) * K + col);
        }
        #pragma unroll
        for (int i = 0; i < 2; i++) {               // B: 512 chunks
            int c = t + 256 * i;
            int kr = c >> 5, col = (c & 31) * 4;
            cpa16(sb + 40960u + (unsigned)(kr * 136 + col) * 4u,
                  Xb + (size_t)kr * NPIX + n0 + col);
        }
        CP_COMMIT();
    }

    float acc[4][8][4];
    #pragma unroll
    for (int i = 0; i < 4; i++)
        #pragma unroll
        for (int j = 0; j < 8; j++)
            #pragma unroll
            for (int q = 0; q < 4; q++) acc[i][j][q] = 0.0f;

    for (int it = 0; it < NT; it++) {
        int s = it & 1;
        if (it + 1 < NT) {
            int k0n = (it + 1) << 4, sn = (it + 1) & 1;
            #pragma unroll
            for (int i = 0; i < 4; i++) {
                int c = t + 256 * i;
                int row = c >> 2, col = (c & 3) * 4;
                cpa16(sb + (unsigned)(sn * 5120 + row * 20 + col) * 4u,
                      W + (size_t)(m0 + row) * K + k0n + col);
            }
            #pragma unroll
            for (int i = 0; i < 2; i++) {
                int c = t + 256 * i;
                int kr = c >> 5, col = (c & 31) * 4;
                cpa16(sb + 40960u + (unsigned)(sn * 2176 + kr * 136 + col) * 4u,
                      Xb + (size_t)(k0n + kr) * NPIX + n0 + col);
            }
            CP_COMMIT();
            CP_WAIT1();
        } else {
            CP_WAIT0();
        }
        __syncthreads();

        const unsigned* A = Asm + s * 5120;
        const unsigned* B = Bsm + s * 2176;
        #pragma unroll
        for (int k8 = 0; k8 < 16; k8 += 8) {
            unsigned af[4][4], bf[8][2];
            #pragma unroll
            for (int mf = 0; mf < 4; mf++) {
                int m = wm + mf * 16 + g;
                int kk = k8 + tig;
                af[mf][0] = A[m * 20 + kk];
                af[mf][1] = A[(m + 8) * 20 + kk];
                af[mf][2] = A[m * 20 + kk + 4];
                af[mf][3] = A[(m + 8) * 20 + kk + 4];
            }
            #pragma unroll
            for (int nf = 0; nf < 8; nf++) {
                int n = wn + nf * 8 + g;
                bf[nf][0] = B[(k8 + tig) * 136 + n];
                bf[nf][1] = B[(k8 + tig + 4) * 136 + n];
            }
            #pragma unroll
            for (int mf = 0; mf < 4; mf++)
                #pragma unroll
                for (int nf = 0; nf < 8; nf++)
                    mma_tf32(acc[mf][nf], af[mf][0], af[mf][1], af[mf][2], af[mf][3],
                             bf[nf][0], bf[nf][1]);
        }
        __syncthreads();
    }

    #pragma unroll
    for (int mf = 0; mf < 4; mf++) {
        int row = m0 + wm + mf * 16 + g;
        float bv0 = bias[row], bv1 = bias[row + 8];
        #pragma unroll
        for (int nf = 0; nf < 8; nf++) {
            int col = n0 + wn + nf * 8 + tig * 2;
            float v00 = acc[mf][nf][0] + bv0, v01 = acc[mf][nf][1] + bv0;
            float v10 = acc[mf][nf][2] + bv1, v11 = acc[mf][nf][3] + bv1;
            float2 o0, o1;
            if (round_out) {
                o0 = make_float2(__uint_as_float(f2tf(v00)), __uint_as_float(f2tf(v01)));
                o1 = make_float2(__uint_as_float(f2tf(v10)), __uint_as_float(f2tf(v11)));
            } else {
                o0 = make_float2(v00, v01);
                o1 = make_float2(v10, v11);
            }
            *(float2*)(Yb + (size_t)row * NPIX + col) = o0;
            *(float2*)(Yb + (size_t)(row + 8) * NPIX + col) = o1;
        }
    }
}

// attn[bh][n][m] = (sum_d q[d][n]*k[d][m]) / scale
// M = n = 256 (full), N = m 128x2. A = q k-major [16][256] str 264;
// B = k k-major [16][128] str 136.  grid (2, 256)
__global__ __launch_bounds__(256) void attn_mma3(const float* __restrict__ scale)
{
    extern __shared__ char smem[];
    const uint32_t sb = smem_u32(smem);
    unsigned* Asm = (unsigned*)smem;                    // 2 x 16*264
    unsigned* Bsm = (unsigned*)(smem + 33792);          // 2 x 16*136

    const int bh = blockIdx.y;
    const unsigned* q  = g_q + (size_t)bh * 65536;
    const unsigned* kp = g_k + (size_t)bh * 65536;
    float*          out = g_attn + (size_t)bh * 65536;
    const int c0 = blockIdx.x * 128;

    const int t = threadIdx.x, lane = t & 31, wid = t >> 5;
    const int g = lane >> 2, tig = lane & 3;
    const int wm = (wid >> 1) * 64, wn = (wid & 1) * 64;

    float inv = 1.0f / __ldg(scale);

    {
        #pragma unroll
        for (int i = 0; i < 4; i++) {               // A: 16x256 = 1024 chunks
            int c = t + 256 * i;
            int kr = c >> 6, col = (c & 63) * 4;
            cpa16(sb + (unsigned)(kr * 264 + col) * 4u,
                  q + (size_t)kr * 256 + col);
        }
        #pragma unroll
        for (int i = 0; i < 2; i++) {               // B: 512 chunks
            int c = t + 256 * i;
            int kr = c >> 5, col = (c & 31) * 4;
            cpa16(sb + 33792u + (unsigned)(kr * 136 + col) * 4u,
                  kp + (size_t)kr * 256 + c0 + col);
        }
        CP_COMMIT();
    }

    float acc[4][8][4];
    #pragma unroll
    for (int i = 0; i < 4; i++)
        #pragma unroll
        for (int j = 0; j < 8; j++)
            #pragma unroll
            for (int q2 = 0; q2 < 4; q2++) acc[i][j][q2] = 0.0f;

    const int NT = 16;   // K = 256
    for (int it = 0; it < NT; it++) {
        int s = it & 1;
        if (it + 1 < NT) {
            int k0n = (it + 1) << 4, sn = (it + 1) & 1;
            #pragma unroll
            for (int i = 0; i < 4; i++) {
                int c = t + 256 * i;
                int kr = c >> 6, col = (c & 63) * 4;
                cpa16(sb + (unsigned)(sn * 4224 + kr * 264 + col) * 4u,
                      q + (size_t)(k0n + kr) * 256 + col);
            }
            #pragma unroll
            for (int i = 0; i < 2; i++) {
                int c = t + 256 * i;
                int kr = c >> 5, col = (c & 31) * 4;
                cpa16(sb + 33792u + (unsigned)(sn * 2176 + kr * 136 + col) * 4u,
                      kp + (size_t)(k0n + kr) * 256 + c0 + col);
            }
            CP_COMMIT();
            CP_WAIT1();
        } else {
            CP_WAIT0();
        }
        __syncthreads();

        const unsigned* A = Asm + s * 4224;
        const unsigned* B = Bsm + s * 2176;
        #pragma unroll
        for (int k8 = 0; k8 < 16; k8 += 8) {
            unsigned af[4][4], bf[8][2];
            #pragma unroll
            for (int mf = 0; mf < 4; mf++) {
                int m = wm + mf * 16 + g;
                af[mf][0] = A[(k8 + tig) * 264 + m];
                af[mf][1] = A[(k8 + tig) * 264 + m + 8];
                af[mf][2] = A[(k8 + tig + 4) * 264 + m];
                af[mf][3] = A[(k8 + tig + 4) * 264 + m + 8];
            }
            #pragma unroll
            for (int nf = 0; nf < 8; nf++) {
                int n = wn + nf * 8 + g;
                bf[nf][0] = B[(k8 + tig) * 136 + n];
                bf[nf][1] = B[(k8 + tig + 4) * 136 + n];
            }
            #pragma unroll
            for (int mf = 0; mf < 4; mf++)
                #pragma unroll
                for (int nf = 0; nf < 8; nf++)
                    mma_tf32(acc[mf][nf], af[mf][0], af[mf][1], af[mf][2], af[mf][3],
                             bf[nf][0], bf[nf][1]);
        }
        __syncthreads();
    }

    #pragma unroll
    for (int mf = 0; mf < 4; mf++) {
        int row = wm + mf * 16 + g;
        #pragma unroll
        for (int nf = 0; nf < 8; nf++) {
            int col = c0 + wn + nf * 8 + tig * 2;
            float2 o0 = make_float2(acc[mf][nf][0] * inv, acc[mf][nf][1] * inv);
            float2 o1 = make_float2(acc[mf][nf][2] * inv, acc[mf][nf][3] * inv);
            *(float2*)(out + (size_t)row * 256 + col) = o0;
            *(float2*)(out + (size_t)(row + 8) * 256 + col) = o1;
        }
    }
}

// sparse mix + softmax: 1 warp per attn row, 8 rows/block, shuffle reductions
__global__ __launch_bounds__(256) void mix_softmax()
{
    __shared__ float arow[8][256];
    const int t = threadIdx.x, lane = t & 31, wid = t >> 5;
    const size_t row = (size_t)blockIdx.x * 8 + wid;

    const float* src = g_attn + row * 256;
    #pragma unroll
    for (int i = 0; i < 8; i++) arow[wid][lane + 32 * i] = src[lane + 32 * i];
    __syncwarp();

    float sp[8];
    #pragma unroll
    for (int j = 0; j < 8; j++) {
        int p = lane + 32 * j;
        int c = g_csc_cnt[p];
        const int*   ri = g_csc_row + p * 256;
        const float* rv = g_csc_val + p * 256;
        float s = 0.0f;
        for (int jj = 0; jj < c; jj++) s += arow[wid][ri[jj]] * rv[jj];
        sp[j] = s;
    }

    float mx = sp[0];
    #pragma unroll
    for (int j = 1; j < 8; j++) mx = fmaxf(mx, sp[j]);
    #pragma unroll
    for (int o = 16; o > 0; o >>= 1) mx = fmaxf(mx, __shfl_xor_sync(0xFFFFFFFF, mx, o));

    float e[8];
    float sum = 0.0f;
    #pragma unroll
    for (int j = 0; j < 8; j++) { e[j] = __expf(sp[j] - mx); sum += e[j]; }
    #pragma unroll
    for (int o = 16; o > 0; o >>= 1) sum += __shfl_xor_sync(0xFFFFFFFF, sum, o);
    float inv = 1.0f / sum;

    unsigned* dst = g_sattn + row * 256;
    #pragma unroll
    for (int j = 0; j < 8; j++) dst[lane + 32 * j] = f2tf(e[j] * inv);
}

// ao[d][n] = sum_m v[d][m] * sattn[n][m]
// M = d = 256 (full), N = n 128x2. A = v row-major [256][16] str 20;
// B = sa row-major [128][16] str 20.  grid (2, 256)
__global__ __launch_bounds__(256) void av_mma3()
{
    extern __shared__ char smem[];
    const uint32_t sb = smem_u32(smem);
    unsigned* Asm = (unsigned*)smem;                    // 2 x 256*20
    unsigned* Bsm = (unsigned*)(smem + 40960);          // 2 x 128*20

    const int bh = blockIdx.y;
    const unsigned* v  = g_v     + (size_t)bh * 65536;
    const unsigned* sa = g_sattn + (size_t)bh * 65536;
    unsigned*       ao = g_ao    + (size_t)bh * 65536;
    const int c0 = blockIdx.x * 128;

    const int t = threadIdx.x, lane = t & 31, wid = t >> 5;
    const int g = lane >> 2, tig = lane & 3;
    const int wm = (wid >> 1) * 64, wn = (wid & 1) * 64;

    {
        #pragma unroll
        for (int i = 0; i < 4; i++) {               // A: 1024 chunks
            int c = t + 256 * i;
            int row = c >> 2, col = (c & 3) * 4;
            cpa16(sb + (unsigned)(row * 20 + col) * 4u,
                  v + (size_t)row * 256 + col);
        }
        #pragma unroll
        for (int i = 0; i < 2; i++) {               // B: 512 chunks
            int c = t + 256 * i;
            int row = c >> 2, col = (c & 3) * 4;
            cpa16(sb + 40960u + (unsigned)(row * 20 + col) * 4u,
                  sa + (size_t)(c0 + row) * 256 + col);
        }
        CP_COMMIT();
    }

    float acc[4][8][4];
    #pragma unroll
    for (int i = 0; i < 4; i++)
        #pragma unroll
        for (int j = 0; j < 8; j++)
            #pragma unroll
            for (int q2 = 0; q2 < 4; q2++) acc[i][j][q2] = 0.0f;

    const int NT = 16;
    for (int it = 0; it < NT; it++) {
        int s = it & 1;
        if (it + 1 < NT) {
            int k0n = (it + 1) << 4, sn = (it + 1) & 1;
            #pragma unroll
            for (int i = 0; i < 4; i++) {
                int c = t + 256 * i;
                int row = c >> 2, col = (c & 3) * 4;
                cpa16(sb + (unsigned)(sn * 5120 + row * 20 + col) * 4u,
                      v + (size_t)row * 256 + k0n + col);
            }
            #pragma unroll
            for (int i = 0; i < 2; i++) {
                int c = t + 256 * i;
                int row = c >> 2, col = (c & 3) * 4;
                cpa16(sb + 40960u + (unsigned)(sn * 2560 + row * 20 + col) * 4u,
                      sa + (size_t)(c0 + row) * 256 + k0n + col);
            }
            CP_COMMIT();
            CP_WAIT1();
        } else {
            CP_WAIT0();
        }
        __syncthreads();

        const unsigned* A = Asm + s * 5120;
        const unsigned* B = Bsm + s * 2560;
        #pragma unroll
        for (int k8 = 0; k8 < 16; k8 += 8) {
            unsigned af[4][4], bf[8][2];
            #pragma unroll
            for (int mf = 0; mf < 4; mf++) {
                int m = wm + mf * 16 + g;
                int kk = k8 + tig;
                af[mf][0] = A[m * 20 + kk];
                af[mf][1] = A[(m + 8) * 20 + kk];
                af[mf][2] = A[m * 20 + kk + 4];
                af[mf][3] = A[(m + 8) * 20 + kk + 4];
            }
            #pragma unroll
            for (int nf = 0; nf < 8; nf++) {
                int n = wn + nf * 8 + g;
                int kk = k8 + tig;
                bf[nf][0] = B[n * 20 + kk];
                bf[nf][1] = B[n * 20 + kk + 4];
            }
            #pragma unroll
            for (int mf = 0; mf < 4; mf++)
                #pragma unroll
                for (int nf = 0; nf < 8; nf++)
                    mma_tf32(acc[mf][nf], af[mf][0], af[mf][1], af[mf][2], af[mf][3],
                             bf[nf][0], bf[nf][1]);
        }
        __syncthreads();
    }

    #pragma unroll
    for (int mf = 0; mf < 4; mf++) {
        int row = wm + mf * 16 + g;
        #pragma unroll
        for (int nf = 0; nf < 8; nf++) {
            int col = c0 + wn + nf * 8 + tig * 2;
            uint2 o0 = make_uint2(f2tf(acc[mf][nf][0]), f2tf(acc[mf][nf][1]));
            uint2 o1 = make_uint2(f2tf(acc[mf][nf][2]), f2tf(acc[mf][nf][3]));
            *(uint2*)(ao + (size_t)row * 256 + col) = o0;
            *(uint2*)(ao + (size_t)(row + 8) * 256 + col) = o1;
        }
    }
}

// ---------------------------------------------------------------------------
extern "C" void kernel_launch(void* const* d_in, const int* in_sizes, int n_in,
                              void* d_out, int out_size)
{
    const float* x     = (const float*)d_in[0];
    const float* Wq    = (const float*)d_in[1];
    const float* bq    = (const float*)d_in[2];
    const float* Wk    = (const float*)d_in[3];
    const float* bk    = (const float*)d_in[4];
    const float* Wv    = (const float*)d_in[5];
    const float* bv    = (const float*)d_in[6];
    const float* Wo    = (const float*)d_in[7];
    const float* bo    = (const float*)d_in[8];
    const float* coeff = (const float*)d_in[9];
    const float* scale = (const float*)d_in[10];
    float* out = (float*)d_out;

    unsigned *pxc, *pwq, *pwk, *pwv, *pwo, *pq, *pk, *pv, *pao;
    cudaGetSymbolAddress((void**)&pxc, g_xc);
    cudaGetSymbolAddress((void**)&pwq, g_wqc);
    cudaGetSymbolAddress((void**)&pwk, g_wkc);
    cudaGetSymbolAddress((void**)&pwv, g_wvc);
    cudaGetSymbolAddress((void**)&pwo, g_woc);
    cudaGetSymbolAddress((void**)&pq,  g_q);
    cudaGetSymbolAddress((void**)&pk,  g_k);
    cudaGetSymbolAddress((void**)&pv,  g_v);
    cudaGetSymbolAddress((void**)&pao, g_ao);

    // dynamic smem caps (idempotent; no static guards)
    cudaFuncSetAttribute(conv_mma3, cudaFuncAttributeMaxDynamicSharedMemorySize, 58368);
    cudaFuncSetAttribute(attn_mma3, cudaFuncAttributeMaxDynamicSharedMemorySize, 51200);
    cudaFuncSetAttribute(av_mma3,   cudaFuncAttributeMaxDynamicSharedMemorySize, 61440);

    // pre-convert operands to tf32 bits
    {
        int nx = BATCH * CIN * NPIX / 4;
        cvt_tf32<<<(nx + 255) / 256, 256>>>((const float4*)x, (uint4*)pxc, nx);
        int nw = COUT * CIN / 4;
        cvt_tf32<<<(nw + 255) / 256, 256>>>((const float4*)Wq, (uint4*)pwq, nw);
        cvt_tf32<<<(nw + 255) / 256, 256>>>((const float4*)Wk, (uint4*)pwk, nw);
        cvt_tf32<<<(nw + 255) / 256, 256>>>((const float4*)Wv, (uint4*)pwv, nw);
        int no = COUT * COUT / 4;
        cvt_tf32<<<(no + 255) / 256, 256>>>((const float4*)Wo, (uint4*)pwo, no);
    }

    sparsify_topk<<<256, 256>>>(coeff);
    build_csc<<<1, 256>>>();

    dim3 gconv(NPIX / 128, COUT / 256, BATCH);   // (2, 8, 32)
    conv_mma3<<<gconv, 256, 58368>>>(pwq, bq, pxc, (float*)pq, CIN, 1);
    conv_mma3<<<gconv, 256, 58368>>>(pwk, bk, pxc, (float*)pk, CIN, 1);
    conv_mma3<<<gconv, 256, 58368>>>(pwv, bv, pxc, (float*)pv, CIN, 1);

    attn_mma3<<<dim3(2, BATCH * HEADS), 256, 51200>>>(scale);
    mix_softmax<<<BATCH * HEADS * NPIX / 8, 256>>>();
    av_mma3<<<dim3(2, BATCH * HEADS), 256, 61440>>>();

    conv_mma3<<<gconv, 256, 58368>>>(pwo, bo, pao, out, COUT, 0);
}

// round 7
// speedup vs baseline: 1.7317x; 1.7317x over previous
#include <cuda_runtime.h>
#include <cuda_fp16.h>
#include <cstdint>

#define BATCH 32
#define CIN   512
#define COUT  2048
#define HEADS 8
#define NPIX  256
#define SPARSITY 7

// fp16 operand buffers
__device__ __half g_xt16 [BATCH * NPIX * CIN];    // [b][n][c]
__device__ __half g_wq16 [COUT * CIN];
__device__ __half g_wk16 [COUT * CIN];
__device__ __half g_wv16 [COUT * CIN];
__device__ __half g_wo16 [COUT * COUT];
__device__ __half g_q16  [BATCH * NPIX * COUT];   // [b][n][2048]
__device__ __half g_k16  [BATCH * NPIX * COUT];   // [b][n][2048]
__device__ __half g_v16  [BATCH * COUT * NPIX];   // [b][m][n]
__device__ __half g_sa16 [BATCH * HEADS * NPIX * NPIX]; // [bh][n][m]
__device__ __half g_aot16[BATCH * NPIX * COUT];   // [b][n][2048]
__device__ float  g_attn [BATCH * HEADS * NPIX * NPIX]; // [bh][n][m] fp32

__device__ int   g_t7i[256 * SPARSITY];
__device__ float g_t7v[256 * SPARSITY];
__device__ int   g_csc_row[256 * 256];
__device__ float g_csc_val[256 * 256];
__device__ int   g_csc_cnt[256];

// ---------------------------------------------------------------------------
__device__ __forceinline__ void mma_f16(float c[4],
    unsigned a0, unsigned a1, unsigned a2, unsigned a3,
    unsigned b0, unsigned b1)
{
    asm volatile(
        "mma.sync.aligned.m16n8k16.row.col.f32.f16.f16.f32 "
        "{%0,%1,%2,%3}, {%4,%5,%6,%7}, {%8,%9}, {%0,%1,%2,%3};"
        : "+f"(c[0]), "+f"(c[1]), "+f"(c[2]), "+f"(c[3])
        : "r"(a0), "r"(a1), "r"(a2), "r"(a3), "r"(b0), "r"(b1));
}

__device__ __forceinline__ void cpa16(unsigned saddr, const void* gptr) {
    asm volatile("cp.async.cg.shared.global [%0], [%1], 16;\n"
                 :: "r"(saddr), "l"(gptr));
}
#define CP_COMMIT() asm volatile("cp.async.commit_group;\n")
#define CP_WAIT1()  asm volatile("cp.async.wait_group 1;\n")
#define CP_WAIT0()  asm volatile("cp.async.wait_group 0;\n")

__device__ __forceinline__ uint32_t smem_u32(const void* p) {
    uint32_t a;
    asm("{ .reg .u64 t; cvta.to.shared.u64 t, %1; cvt.u32.u64 %0, t; }"
        : "=r"(a) : "l"(p));
    return a;
}

// ---------------------------------------------------------------------------
// pre-passes
__global__ void cvt_fp16(const float4* __restrict__ src, __half2* __restrict__ dst, int n4) {
    int i = blockIdx.x * blockDim.x + threadIdx.x;
    if (i < n4) {
        float4 v = src[i];
        dst[2 * i]     = __floats2half2_rn(v.x, v.y);
        dst[2 * i + 1] = __floats2half2_rn(v.z, v.w);
    }
}

// x[b][c][n] fp32 -> xt[b][n][c] fp16
__global__ void tr_cvt16(const float* __restrict__ in, __half* __restrict__ out,
                         int C, int N) {
    __shared__ float s[32][33];
    int b = blockIdx.z;
    const float* ib = in  + (size_t)b * C * N;
    __half*      ob = out + (size_t)b * N * C;
    int c0 = blockIdx.x * 32, n0 = blockIdx.y * 32;
    int tx = threadIdx.x, ty = threadIdx.y;
    #pragma unroll
    for (int i = 0; i < 4; i++)
        s[ty + 8 * i][tx] = ib[(size_t)(c0 + ty + 8 * i) * N + n0 + tx];
    __syncthreads();
    #pragma unroll
    for (int i = 0; i < 4; i++)
        ob[(size_t)(n0 + ty + 8 * i) * C + c0 + tx] = __float2half(s[tx][ty + 8 * i]);
}

// ---------------------------------------------------------------------------
__global__ void sparsify_topk(const float* __restrict__ coeff) {
    int r = blockIdx.x;
    int t = threadIdx.x;
    __shared__ float av[2048];
    __shared__ float rv[256];
    __shared__ int   ri[256];

    const float* row = coeff + (size_t)r * 2048;
    for (int j = t; j < 2048; j += 256) av[j] = fabsf(row[j]);
    __syncthreads();

    for (int it = 0; it < SPARSITY; it++) {
        float best = -1.0f; int bi = 1 << 30;
        for (int j = t; j < 2048; j += 256) {
            float v = av[j];
            if (v > best) { best = v; bi = j; }
        }
        rv[t] = best; ri[t] = bi;
        __syncthreads();
        for (int s = 128; s > 0; s >>= 1) {
            if (t < s) {
                if (rv[t + s] > rv[t] || (rv[t + s] == rv[t] && ri[t + s] < ri[t])) {
                    rv[t] = rv[t + s]; ri[t] = ri[t + s];
                }
            }
            __syncthreads();
        }
        if (t == 0) {
            int idx = ri[0];
            g_t7i[r * SPARSITY + it] = idx;
            g_t7v[r * SPARSITY + it] = row[idx];
            av[idx] = -2.0f;
        }
        __syncthreads();
    }
}

__global__ void build_csc() {
    int p = threadIdx.x;
    int cnt = 0;
    for (int r = 0; r < 256; r++) {
        #pragma unroll
        for (int j = 0; j < SPARSITY; j++) {
            if (g_t7i[r * SPARSITY + j] == p) {
                g_csc_row[p * 256 + cnt] = r;
                g_csc_val[p * 256 + cnt] = g_t7v[r * SPARSITY + j];
                cnt++;
            }
        }
    }
    g_csc_cnt[p] = cnt;
}

// ---------------------------------------------------------------------------
// Unified fp16 GEMM:  C[M][N] = A[M][K] * B[N][K]^T  (+ epilogue by mode)
// Block 128x128, BK=32, 256 thr = 8 warps (2m x 4n), warp 64x32 (4mf x 4nf),
// mma m16n8k16. Smem tiles [128][40 halves] (32 used + 8 pad), 2-stage cp.async.
//
// modes: 0 conv->q/k   (u16 scatter to [b][n][2048], +bias)
//        1 conv->v     (half2 to [b][m][n], +bias)
//        2 conv->out   (float2 to [b][m][n], +bias)
//        3 attn        (float2 to [bh][n][m], *1/scale)
//        4 av->aot     (u16 scatter to [b][n][2048] at col h*256+m, no bias)
// ---------------------------------------------------------------------------
__global__ __launch_bounds__(256) void hgemm(
    const __half* __restrict__ A, const __half* __restrict__ B, void* __restrict__ C,
    int K, int lda, int ldb, int mode,
    const float* __restrict__ bias, const float* __restrict__ scale)
{
    extern __shared__ char smem[];
    const uint32_t sb = smem_u32(smem);

    const int z  = blockIdx.z;
    const int m0 = blockIdx.y * 128;
    const int n0 = blockIdx.x * 128;

    const __half *Ap, *Bp;
    if (mode == 3) {
        int b = z >> 3, h = z & 7;
        Ap = A + (size_t)b * 524288 + h * 256;
        Bp = B + (size_t)b * 524288 + h * 256;
    } else if (mode == 4) {
        int b = z >> 3, h = z & 7;
        Ap = A + (size_t)b * 524288 + h * 65536;
        Bp = B + (size_t)z * 65536;
    } else {
        Ap = A;
        Bp = B + (size_t)z * NPIX * K;
    }

    const int t = threadIdx.x, lane = t & 31, wid = t >> 5;
    const int g = lane >> 2, tig = lane & 3;
    const int wm = (wid >> 2) * 64, wn = (wid & 3) * 32;

    const int NT = K >> 5;

    // stage copy: A 512 chunks + B 512 chunks, 4 per thread
    {
        #pragma unroll
        for (int i = 0; i < 2; i++) {
            int c = t + 256 * i;
            int row = c >> 2, col16 = c & 3;
            cpa16(sb + (unsigned)(row * 80 + col16 * 16),
                  Ap + (size_t)(m0 + row) * lda + col16 * 8);
        }
        #pragma unroll
        for (int i = 0; i < 2; i++) {
            int c = t + 256 * i;
            int row = c >> 2, col16 = c & 3;
            cpa16(sb + 20480u + (unsigned)(row * 80 + col16 * 16),
                  Bp + (size_t)(n0 + row) * ldb + col16 * 8);
        }
        CP_COMMIT();
    }

    float acc[4][4][4];
    #pragma unroll
    for (int i = 0; i < 4; i++)
        #pragma unroll
        for (int j = 0; j < 4; j++)
            #pragma unroll
            for (int q = 0; q < 4; q++) acc[i][j][q] = 0.0f;

    for (int it = 0; it < NT; it++) {
        int s = it & 1;
        if (it + 1 < NT) {
            int k0n = (it + 1) << 5, sn = (it + 1) & 1;
            #pragma unroll
            for (int i = 0; i < 2; i++) {
                int c = t + 256 * i;
                int row = c >> 2, col16 = c & 3;
                cpa16(sb + (unsigned)(sn * 10240 + row * 80 + col16 * 16),
                      Ap + (size_t)(m0 + row) * lda + k0n + col16 * 8);
            }
            #pragma unroll
            for (int i = 0; i < 2; i++) {
                int c = t + 256 * i;
                int row = c >> 2, col16 = c & 3;
                cpa16(sb + 20480u + (unsigned)(sn * 10240 + row * 80 + col16 * 16),
                      Bp + (size_t)(n0 + row) * ldb + k0n + col16 * 8);
            }
            CP_COMMIT();
            CP_WAIT1();
        } else {
            CP_WAIT0();
        }
        __syncthreads();

        const unsigned* Au = (const unsigned*)(smem + s * 10240);
        const unsigned* Bu = (const unsigned*)(smem + 20480 + s * 10240);
        #pragma unroll
        for (int kh = 0; kh < 16; kh += 8) {      // two k16 steps (u32 offsets 0, 8)
            unsigned af[4][4], bf[4][2];
            #pragma unroll
            for (int mf = 0; mf < 4; mf++) {
                int m = wm + mf * 16 + g;
                af[mf][0] = Au[m * 20 + kh + tig];
                af[mf][1] = Au[(m + 8) * 20 + kh + tig];
                af[mf][2] = Au[m * 20 + kh + 4 + tig];
                af[mf][3] = Au[(m + 8) * 20 + kh + 4 + tig];
            }
            #pragma unroll
            for (int nf = 0; nf < 4; nf++) {
                int n = wn + nf * 8 + g;
                bf[nf][0] = Bu[n * 20 + kh + tig];
                bf[nf][1] = Bu[n * 20 + kh + 4 + tig];
            }
            #pragma unroll
            for (int mf = 0; mf < 4; mf++)
                #pragma unroll
                for (int nf = 0; nf < 4; nf++)
                    mma_f16(acc[mf][nf], af[mf][0], af[mf][1], af[mf][2], af[mf][3],
                            bf[nf][0], bf[nf][1]);
        }
        __syncthreads();
    }

    // epilogue
    const float inv = (mode == 3) ? (1.0f / __ldg(scale)) : 1.0f;
    #pragma unroll
    for (int mf = 0; mf < 4; mf++) {
        int r = wm + mf * 16 + g;           // local row
        int m = m0 + r;                     // global row
        float bv0 = 0.0f, bv1 = 0.0f;
        if (mode <= 2) { bv0 = bias[m]; bv1 = bias[m + 8]; }
        #pragma unroll
        for (int nf = 0; nf < 4; nf++) {
            int cc = wn + nf * 8 + 2 * tig; // local col
            int n = n0 + cc;                // global col
            float v00 = acc[mf][nf][0] + bv0, v01 = acc[mf][nf][1] + bv0;
            float v10 = acc[mf][nf][2] + bv1, v11 = acc[mf][nf][3] + bv1;
            if (mode == 0) {
                __half* Ch = (__half*)C + (size_t)z * 524288;
                Ch[(size_t)n * 2048 + m]           = __float2half(v00);
                Ch[(size_t)(n + 1) * 2048 + m]     = __float2half(v01);
                Ch[(size_t)n * 2048 + m + 8]       = __float2half(v10);
                Ch[(size_t)(n + 1) * 2048 + m + 8] = __float2half(v11);
            } else if (mode == 1) {
                __half2* Ch = (__half2*)((__half*)C + (size_t)z * 524288);
                Ch[((size_t)m * 256 + n) >> 1]       = __floats2half2_rn(v00, v01);
                Ch[((size_t)(m + 8) * 256 + n) >> 1] = __floats2half2_rn(v10, v11);
            } else if (mode == 2) {
                float* Cf = (float*)C + (size_t)z * 524288;
                *(float2*)(Cf + (size_t)m * 256 + n)       = make_float2(v00, v01);
                *(float2*)(Cf + (size_t)(m + 8) * 256 + n) = make_float2(v10, v11);
            } else if (mode == 3) {
                float* Cf = (float*)C + (size_t)z * 65536;
                *(float2*)(Cf + (size_t)m * 256 + n)       = make_float2(v00 * inv, v01 * inv);
                *(float2*)(Cf + (size_t)(m + 8) * 256 + n) = make_float2(v10 * inv, v11 * inv);
            } else {
                int b = z >> 3, h = z & 7;
                __half* Ch = (__half*)C + (size_t)b * 524288 + h * 256;
                Ch[(size_t)n * 2048 + m]           = __float2half(v00);
                Ch[(size_t)(n + 1) * 2048 + m]     = __float2half(v01);
                Ch[(size_t)n * 2048 + m + 8]       = __float2half(v10);
                Ch[(size_t)(n + 1) * 2048 + m + 8] = __float2half(v11);
            }
        }
    }
}

// ---------------------------------------------------------------------------
// sparse mix + softmax: 1 warp per attn row, fp32 in, fp16 out
__global__ __launch_bounds__(256) void mix_softmax()
{
    __shared__ float arow[8][256];
    const int t = threadIdx.x, lane = t & 31, wid = t >> 5;
    const size_t row = (size_t)blockIdx.x * 8 + wid;

    const float* src = g_attn + row * 256;
    #pragma unroll
    for (int i = 0; i < 8; i++) arow[wid][lane + 32 * i] = src[lane + 32 * i];
    __syncwarp();

    float sp[8];
    #pragma unroll
    for (int j = 0; j < 8; j++) {
        int p = lane + 32 * j;
        int c = g_csc_cnt[p];
        const int*   ri = g_csc_row + p * 256;
        const float* rv = g_csc_val + p * 256;
        float s = 0.0f;
        for (int jj = 0; jj < c; jj++) s += arow[wid][ri[jj]] * rv[jj];
        sp[j] = s;
    }

    float mx = sp[0];
    #pragma unroll
    for (int j = 1; j < 8; j++) mx = fmaxf(mx, sp[j]);
    #pragma unroll
    for (int o = 16; o > 0; o >>= 1) mx = fmaxf(mx, __shfl_xor_sync(0xFFFFFFFF, mx, o));

    float e[8];
    float sum = 0.0f;
    #pragma unroll
    for (int j = 0; j < 8; j++) { e[j] = __expf(sp[j] - mx); sum += e[j]; }
    #pragma unroll
    for (int o = 16; o > 0; o >>= 1) sum += __shfl_xor_sync(0xFFFFFFFF, sum, o);
    float inv = 1.0f / sum;

    __half* dst = g_sa16 + row * 256;
    #pragma unroll
    for (int j = 0; j < 8; j++) dst[lane + 32 * j] = __float2half(e[j] * inv);
}

// ---------------------------------------------------------------------------
extern "C" void kernel_launch(void* const* d_in, const int* in_sizes, int n_in,
                              void* d_out, int out_size)
{
    const float* x     = (const float*)d_in[0];
    const float* Wq    = (const float*)d_in[1];
    const float* bq    = (const float*)d_in[2];
    const float* Wk    = (const float*)d_in[3];
    const float* bk    = (const float*)d_in[4];
    const float* Wv    = (const float*)d_in[5];
    const float* bv    = (const float*)d_in[6];
    const float* Wo    = (const float*)d_in[7];
    const float* bo    = (const float*)d_in[8];
    const float* coeff = (const float*)d_in[9];
    const float* scale = (const float*)d_in[10];
    float* out = (float*)d_out;

    __half *pxt, *pwq, *pwk, *pwv, *pwo, *pq, *pk, *pv, *psa, *paot;
    float *pattn;
    cudaGetSymbolAddress((void**)&pxt,  g_xt16);
    cudaGetSymbolAddress((void**)&pwq,  g_wq16);
    cudaGetSymbolAddress((void**)&pwk,  g_wk16);
    cudaGetSymbolAddress((void**)&pwv,  g_wv16);
    cudaGetSymbolAddress((void**)&pwo,  g_wo16);
    cudaGetSymbolAddress((void**)&pq,   g_q16);
    cudaGetSymbolAddress((void**)&pk,   g_k16);
    cudaGetSymbolAddress((void**)&pv,   g_v16);
    cudaGetSymbolAddress((void**)&psa,  g_sa16);
    cudaGetSymbolAddress((void**)&paot, g_aot16);
    cudaGetSymbolAddress((void**)&pattn, g_attn);

    // operand conversions
    {
        int nw = COUT * CIN / 4;
        cvt_fp16<<<(nw + 255) / 256, 256>>>((const float4*)Wq, (__half2*)pwq, nw);
        cvt_fp16<<<(nw + 255) / 256, 256>>>((const float4*)Wk, (__half2*)pwk, nw);
        cvt_fp16<<<(nw + 255) / 256, 256>>>((const float4*)Wv, (__half2*)pwv, nw);
        int no = COUT * COUT / 4;
        cvt_fp16<<<(no + 255) / 256, 256>>>((const float4*)Wo, (__half2*)pwo, no);
    }
    tr_cvt16<<<dim3(CIN / 32, NPIX / 32, BATCH), dim3(32, 8)>>>(x, pxt, CIN, NPIX);

    sparsify_topk<<<256, 256>>>(coeff);
    build_csc<<<1, 256>>>();

    const int SM = 40960;
    dim3 gconv(2, 16, BATCH);
    hgemm<<<gconv, 256, SM>>>(pwq, pxt, pq, CIN, CIN, CIN, 0, bq, scale);
    hgemm<<<gconv, 256, SM>>>(pwk, pxt, pk, CIN, CIN, CIN, 0, bk, scale);
    hgemm<<<gconv, 256, SM>>>(pwv, pxt, pv, CIN, CIN, CIN, 1, bv, scale);

    hgemm<<<dim3(2, 2, BATCH * HEADS), 256, SM>>>(pq, pk, pattn, 256, 2048, 2048, 3, bq, scale);
    mix_softmax<<<BATCH * HEADS * NPIX / 8, 256>>>();
    hgemm<<<dim3(2, 2, BATCH * HEADS), 256, SM>>>(pv, psa, paot, 256, 256, 256, 4, bq, scale);

    hgemm<<<gconv, 256, SM>>>(pwo, paot, out, COUT, COUT, COUT, 2, bo, scale);
}

// round 8
// speedup vs baseline: 1.8205x; 1.0513x over previous
#include <cuda_runtime.h>
#include <cuda_fp16.h>
#include <cstdint>

#define BATCH 32
#define CIN   512
#define COUT  2048
#define HEADS 8
#define NPIX  256
#define SPARSITY 7

// fp16 operand buffers
__device__ __half g_xt16 [BATCH * NPIX * CIN];    // [b][n][c]
__device__ __half g_wq16 [COUT * CIN];
__device__ __half g_wk16 [COUT * CIN];
__device__ __half g_wv16 [COUT * CIN];
__device__ __half g_wo16 [COUT * COUT];
__device__ __half g_q16  [BATCH * NPIX * COUT];   // [b][n][2048]
__device__ __half g_k16  [BATCH * NPIX * COUT];   // [b][n][2048]
__device__ __half g_v16  [BATCH * COUT * NPIX];   // [b][m][n]
__device__ __half g_sa16 [BATCH * HEADS * NPIX * NPIX]; // [bh][n][m]
__device__ __half g_aot16[BATCH * NPIX * COUT];   // [b][n][2048]
__device__ float  g_attn [BATCH * HEADS * NPIX * NPIX]; // [bh][n][m] fp32

__device__ int   g_t7i[256 * SPARSITY];
__device__ float g_t7v[256 * SPARSITY];
__device__ int   g_csc_row[256 * 256];
__device__ float g_csc_val[256 * 256];
__device__ int   g_csc_cnt[256];

// ---------------------------------------------------------------------------
__device__ __forceinline__ void mma_f16(float c[4],
    unsigned a0, unsigned a1, unsigned a2, unsigned a3,
    unsigned b0, unsigned b1)
{
    asm volatile(
        "mma.sync.aligned.m16n8k16.row.col.f32.f16.f16.f32 "
        "{%0,%1,%2,%3}, {%4,%5,%6,%7}, {%8,%9}, {%0,%1,%2,%3};"
        : "+f"(c[0]), "+f"(c[1]), "+f"(c[2]), "+f"(c[3])
        : "r"(a0), "r"(a1), "r"(a2), "r"(a3), "r"(b0), "r"(b1));
}

__device__ __forceinline__ void ldsm_x4(unsigned& r0, unsigned& r1,
                                        unsigned& r2, unsigned& r3, uint32_t a)
{
    asm volatile("ldmatrix.sync.aligned.m8n8.x4.shared.b16 {%0,%1,%2,%3}, [%4];"
                 : "=r"(r0), "=r"(r1), "=r"(r2), "=r"(r3) : "r"(a));
}

__device__ __forceinline__ void cpa16(unsigned saddr, const void* gptr) {
    asm volatile("cp.async.cg.shared.global [%0], [%1], 16;\n"
                 :: "r"(saddr), "l"(gptr));
}
#define CP_COMMIT() asm volatile("cp.async.commit_group;\n")
#define CP_WAIT2()  asm volatile("cp.async.wait_group 2;\n")
#define CP_WAIT1()  asm volatile("cp.async.wait_group 1;\n")
#define CP_WAIT0()  asm volatile("cp.async.wait_group 0;\n")

__device__ __forceinline__ uint32_t smem_u32(const void* p) {
    uint32_t a;
    asm("{ .reg .u64 t; cvta.to.shared.u64 t, %1; cvt.u32.u64 %0, t; }"
        : "=r"(a) : "l"(p));
    return a;
}

// ---------------------------------------------------------------------------
__global__ void cvt_fp16(const float4* __restrict__ src, __half2* __restrict__ dst, int n4) {
    int i = blockIdx.x * blockDim.x + threadIdx.x;
    if (i < n4) {
        float4 v = src[i];
        dst[2 * i]     = __floats2half2_rn(v.x, v.y);
        dst[2 * i + 1] = __floats2half2_rn(v.z, v.w);
    }
}

__global__ void tr_cvt16(const float* __restrict__ in, __half* __restrict__ out,
                         int C, int N) {
    __shared__ float s[32][33];
    int b = blockIdx.z;
    const float* ib = in  + (size_t)b * C * N;
    __half*      ob = out + (size_t)b * N * C;
    int c0 = blockIdx.x * 32, n0 = blockIdx.y * 32;
    int tx = threadIdx.x, ty = threadIdx.y;
    #pragma unroll
    for (int i = 0; i < 4; i++)
        s[ty + 8 * i][tx] = ib[(size_t)(c0 + ty + 8 * i) * N + n0 + tx];
    __syncthreads();
    #pragma unroll
    for (int i = 0; i < 4; i++)
        ob[(size_t)(n0 + ty + 8 * i) * C + c0 + tx] = __float2half(s[tx][ty + 8 * i]);
}

// ---------------------------------------------------------------------------
__global__ void sparsify_topk(const float* __restrict__ coeff) {
    int r = blockIdx.x;
    int t = threadIdx.x;
    __shared__ float av[2048];
    __shared__ float rv[256];
    __shared__ int   ri[256];

    const float* row = coeff + (size_t)r * 2048;
    for (int j = t; j < 2048; j += 256) av[j] = fabsf(row[j]);
    __syncthreads();

    for (int it = 0; it < SPARSITY; it++) {
        float best = -1.0f; int bi = 1 << 30;
        for (int j = t; j < 2048; j += 256) {
            float v = av[j];
            if (v > best) { best = v; bi = j; }
        }
        rv[t] = best; ri[t] = bi;
        __syncthreads();
        for (int s = 128; s > 0; s >>= 1) {
            if (t < s) {
                if (rv[t + s] > rv[t] || (rv[t + s] == rv[t] && ri[t + s] < ri[t])) {
                    rv[t] = rv[t + s]; ri[t] = ri[t + s];
                }
            }
            __syncthreads();
        }
        if (t == 0) {
            int idx = ri[0];
            g_t7i[r * SPARSITY + it] = idx;
            g_t7v[r * SPARSITY + it] = row[idx];
            av[idx] = -2.0f;
        }
        __syncthreads();
    }
}

__global__ void build_csc() {
    int p = threadIdx.x;
    int cnt = 0;
    for (int r = 0; r < 256; r++) {
        #pragma unroll
        for (int j = 0; j < SPARSITY; j++) {
            if (g_t7i[r * SPARSITY + j] == p) {
                g_csc_row[p * 256 + cnt] = r;
                g_csc_val[p * 256 + cnt] = g_t7v[r * SPARSITY + j];
                cnt++;
            }
        }
    }
    g_csc_cnt[p] = cnt;
}

// ---------------------------------------------------------------------------
// Unified fp16 GEMM:  C[M][N] = A[M][K] * B[N][K]^T
// Block 128x128, BK=32, 8 warps (2m x 4n), warp 64x32, mma m16n8k16,
// ldmatrix fragment loads, 3-stage cp.async.
// Smem per stage: A 128 rows x 80B (64B data + 16B pad), B same -> 20480B.
// 3 stages = 61440B. Epilogue staging reuses smem.
// modes: 0 conv->q/k [n][2048]+bias  1 conv->v [m][n]+bias
//        2 conv->out [m][n]+bias     3 attn [n][m]*inv_scale
//        4 av->aot [n][2048]
// ---------------------------------------------------------------------------
__global__ __launch_bounds__(256) void hgemm(
    const __half* __restrict__ A, const __half* __restrict__ B, void* __restrict__ C,
    int K, int lda, int ldb, int mode,
    const float* __restrict__ bias, const float* __restrict__ scale)
{
    extern __shared__ char smem[];
    const uint32_t sb = smem_u32(smem);

    const int z  = blockIdx.z;
    const int m0 = blockIdx.y * 128;
    const int n0 = blockIdx.x * 128;

    const __half *Ap, *Bp;
    if (mode == 3) {
        int b = z >> 3, h = z & 7;
        Ap = A + (size_t)b * 524288 + h * 256;
        Bp = B + (size_t)b * 524288 + h * 256;
    } else if (mode == 4) {
        int b = z >> 3, h = z & 7;
        Ap = A + (size_t)b * 524288 + h * 65536;
        Bp = B + (size_t)z * 65536;
    } else {
        Ap = A;
        Bp = B + (size_t)z * NPIX * K;
    }

    const int t = threadIdx.x, lane = t & 31, wid = t >> 5;
    const int g = lane >> 2, tig = lane & 3;
    const int wm = (wid >> 2) * 64, wn = (wid & 3) * 32;

    // copy mapping: per tile 512 chunks (row = c>>2, col16 = c&3), 2/thread
    const int cr0 = t >> 2,        cc0 = (t & 3) * 16;        // chunk 0
    const int cr1 = (t + 256) >> 2, cc1 = (t & 3) * 16;       // chunk 1 (row+64)

    // ldmatrix lane addresses (byte offsets within a stage)
    const uint32_t aoff = (uint32_t)(wm + (lane & 15)) * 80u + (uint32_t)(lane >> 4) * 16u;
    const int bq = lane >> 3;
    const uint32_t boff = (uint32_t)(wn + ((bq >> 1) << 3) + (lane & 7)) * 80u
                        + (uint32_t)(bq & 1) * 16u;

    const int NT = K >> 5;

    // prologue: stages 0,1
    #pragma unroll
    for (int s = 0; s < 2; s++) {
        uint32_t sA = sb + (unsigned)s * 20480u;
        uint32_t sB = sA + 10240u;
        cpa16(sA + (unsigned)cr0 * 80u + cc0, Ap + (size_t)(m0 + cr0) * lda + s * 32 + (cc0 >> 1));
        cpa16(sA + (unsigned)cr1 * 80u + cc1, Ap + (size_t)(m0 + cr1) * lda + s * 32 + (cc1 >> 1));
        cpa16(sB + (unsigned)cr0 * 80u + cc0, Bp + (size_t)(n0 + cr0) * ldb + s * 32 + (cc0 >> 1));
        cpa16(sB + (unsigned)cr1 * 80u + cc1, Bp + (size_t)(n0 + cr1) * ldb + s * 32 + (cc1 >> 1));
        CP_COMMIT();
    }

    float acc[4][4][4];
    #pragma unroll
    for (int i = 0; i < 4; i++)
        #pragma unroll
        for (int j = 0; j < 4; j++)
            #pragma unroll
            for (int q = 0; q < 4; q++) acc[i][j][q] = 0.0f;

    for (int it = 0; it < NT; it++) {
        int s = it % 3;
        if (it + 2 < NT) {
            int sn = (it + 2) % 3, k0n = (it + 2) << 5;
            uint32_t sA = sb + (unsigned)sn * 20480u;
            uint32_t sB = sA + 10240u;
            cpa16(sA + (unsigned)cr0 * 80u + cc0, Ap + (size_t)(m0 + cr0) * lda + k0n + (cc0 >> 1));
            cpa16(sA + (unsigned)cr1 * 80u + cc1, Ap + (size_t)(m0 + cr1) * lda + k0n + (cc1 >> 1));
            cpa16(sB + (unsigned)cr0 * 80u + cc0, Bp + (size_t)(n0 + cr0) * ldb + k0n + (cc0 >> 1));
            cpa16(sB + (unsigned)cr1 * 80u + cc1, Bp + (size_t)(n0 + cr1) * ldb + k0n + (cc1 >> 1));
            CP_COMMIT();
            CP_WAIT2();
        } else if (it + 1 < NT) {
            CP_WAIT1();
        } else {
            CP_WAIT0();
        }
        __syncthreads();

        uint32_t sA = sb + (unsigned)s * 20480u + aoff;
        uint32_t sB = sb + (unsigned)s * 20480u + 10240u + boff;
        #pragma unroll
        for (int kb = 0; kb < 2; kb++) {
            unsigned a[4][4], b[2][4];
            #pragma unroll
            for (int mf = 0; mf < 4; mf++)
                ldsm_x4(a[mf][0], a[mf][1], a[mf][2], a[mf][3],
                        sA + (unsigned)mf * 1280u + (unsigned)kb * 32u);
            #pragma unroll
            for (int np = 0; np < 2; np++)
                ldsm_x4(b[np][0], b[np][1], b[np][2], b[np][3],
                        sB + (unsigned)np * 1280u + (unsigned)kb * 32u);
            #pragma unroll
            for (int mf = 0; mf < 4; mf++)
                #pragma unroll
                for (int nf = 0; nf < 4; nf++)
                    mma_f16(acc[mf][nf], a[mf][0], a[mf][1], a[mf][2], a[mf][3],
                            b[nf >> 1][(nf & 1) * 2], b[nf >> 1][(nf & 1) * 2 + 1]);
        }
        __syncthreads();
    }

    // ---------------- epilogues ----------------
    const float inv = (mode == 3) ? (1.0f / __ldg(scale)) : 1.0f;

    if (mode == 0 || mode == 4) {
        // stage C^T in smem [n_local 128][m_local 136 halves], then coalesced u16x8
        __half* st = (__half*)smem;
        #pragma unroll
        for (int mf = 0; mf < 4; mf++) {
            int r = wm + mf * 16 + g;
            float bv0 = 0.0f, bv1 = 0.0f;
            if (mode == 0) { bv0 = bias[m0 + r]; bv1 = bias[m0 + r + 8]; }
            #pragma unroll
            for (int nf = 0; nf < 4; nf++) {
                int cc = wn + nf * 8 + 2 * tig;
                st[(size_t)cc * 136 + r]           = __float2half(acc[mf][nf][0] + bv0);
                st[(size_t)(cc + 1) * 136 + r]     = __float2half(acc[mf][nf][1] + bv0);
                st[(size_t)cc * 136 + r + 8]       = __float2half(acc[mf][nf][2] + bv1);
                st[(size_t)(cc + 1) * 136 + r + 8] = __float2half(acc[mf][nf][3] + bv1);
            }
        }
        __syncthreads();
        __half* Ch;
        if (mode == 0) {
            Ch = (__half*)C + (size_t)z * 524288;
        } else {
            int b = z >> 3, h = z & 7;
            Ch = (__half*)C + (size_t)b * 524288 + h * 256;
        }
        #pragma unroll
        for (int i = 0; i < 8; i++) {
            int c = t + 256 * i;
            int n = c >> 4, col16 = c & 15;
            uint4 val = *(const uint4*)(st + (size_t)n * 136 + col16 * 8);
            *(uint4*)(Ch + (size_t)(n0 + n) * 2048 + m0 + col16 * 8) = val;
        }
        return;
    }

    #pragma unroll
    for (int mf = 0; mf < 4; mf++) {
        int r = wm + mf * 16 + g;
        int m = m0 + r;
        float bv0 = 0.0f, bv1 = 0.0f;
        if (mode <= 2) { bv0 = bias[m]; bv1 = bias[m + 8]; }
        #pragma unroll
        for (int nf = 0; nf < 4; nf++) {
            int cc = wn + nf * 8 + 2 * tig;
            int n = n0 + cc;
            float v00 = acc[mf][nf][0] + bv0, v01 = acc[mf][nf][1] + bv0;
            float v10 = acc[mf][nf][2] + bv1, v11 = acc[mf][nf][3] + bv1;
            if (mode == 1) {
                __half2* Ch = (__half2*)((__half*)C + (size_t)z * 524288);
                Ch[((size_t)m * 256 + n) >> 1]       = __floats2half2_rn(v00, v01);
                Ch[((size_t)(m + 8) * 256 + n) >> 1] = __floats2half2_rn(v10, v11);
            } else if (mode == 2) {
                float* Cf = (float*)C + (size_t)z * 524288;
                *(float2*)(Cf + (size_t)m * 256 + n)       = make_float2(v00, v01);
                *(float2*)(Cf + (size_t)(m + 8) * 256 + n) = make_float2(v10, v11);
            } else {
                float* Cf = (float*)C + (size_t)z * 65536;
                *(float2*)(Cf + (size_t)m * 256 + n)       = make_float2(v00 * inv, v01 * inv);
                *(float2*)(Cf + (size_t)(m + 8) * 256 + n) = make_float2(v10 * inv, v11 * inv);
            }
        }
    }
}

// ---------------------------------------------------------------------------
__global__ __launch_bounds__(256) void mix_softmax()
{
    __shared__ float arow[8][256];
    const int t = threadIdx.x, lane = t & 31, wid = t >> 5;
    const size_t row = (size_t)blockIdx.x * 8 + wid;

    const float* src = g_attn + row * 256;
    #pragma unroll
    for (int i = 0; i < 8; i++) arow[wid][lane + 32 * i] = src[lane + 32 * i];
    __syncwarp();

    float sp[8];
    #pragma unroll
    for (int j = 0; j < 8; j++) {
        int p = lane + 32 * j;
        int c = g_csc_cnt[p];
        const int*   ri = g_csc_row + p * 256;
        const float* rv = g_csc_val + p * 256;
        float s = 0.0f;
        for (int jj = 0; jj < c; jj++) s += arow[wid][ri[jj]] * rv[jj];
        sp[j] = s;
    }

    float mx = sp[0];
    #pragma unroll
    for (int j = 1; j < 8; j++) mx = fmaxf(mx, sp[j]);
    #pragma unroll
    for (int o = 16; o > 0; o >>= 1) mx = fmaxf(mx, __shfl_xor_sync(0xFFFFFFFF, mx, o));

    float e[8];
    float sum = 0.0f;
    #pragma unroll
    for (int j = 0; j < 8; j++) { e[j] = __expf(sp[j] - mx); sum += e[j]; }
    #pragma unroll
    for (int o = 16; o > 0; o >>= 1) sum += __shfl_xor_sync(0xFFFFFFFF, sum, o);
    float inv = 1.0f / sum;

    __half* dst = g_sa16 + row * 256;
    #pragma unroll
    for (int j = 0; j < 8; j++) dst[lane + 32 * j] = __float2half(e[j] * inv);
}

// ---------------------------------------------------------------------------
extern "C" void kernel_launch(void* const* d_in, const int* in_sizes, int n_in,
                              void* d_out, int out_size)
{
    const float* x     = (const float*)d_in[0];
    const float* Wq    = (const float*)d_in[1];
    const float* bq    = (const float*)d_in[2];
    const float* Wk    = (const float*)d_in[3];
    const float* bk    = (const float*)d_in[4];
    const float* Wv    = (const float*)d_in[5];
    const float* bv    = (const float*)d_in[6];
    const float* Wo    = (const float*)d_in[7];
    const float* bo    = (const float*)d_in[8];
    const float* coeff = (const float*)d_in[9];
    const float* scale = (const float*)d_in[10];
    float* out = (float*)d_out;

    __half *pxt, *pwq, *pwk, *pwv, *pwo, *pq, *pk, *pv, *psa, *paot;
    float *pattn;
    cudaGetSymbolAddress((void**)&pxt,  g_xt16);
    cudaGetSymbolAddress((void**)&pwq,  g_wq16);
    cudaGetSymbolAddress((void**)&pwk,  g_wk16);
    cudaGetSymbolAddress((void**)&pwv,  g_wv16);
    cudaGetSymbolAddress((void**)&pwo,  g_wo16);
    cudaGetSymbolAddress((void**)&pq,   g_q16);
    cudaGetSymbolAddress((void**)&pk,   g_k16);
    cudaGetSymbolAddress((void**)&pv,   g_v16);
    cudaGetSymbolAddress((void**)&psa,  g_sa16);
    cudaGetSymbolAddress((void**)&paot, g_aot16);
    cudaGetSymbolAddress((void**)&pattn, g_attn);

    cudaFuncSetAttribute(hgemm, cudaFuncAttributeMaxDynamicSharedMemorySize, 61440);

    {
        int nw = COUT * CIN / 4;
        cvt_fp16<<<(nw + 255) / 256, 256>>>((const float4*)Wq, (__half2*)pwq, nw);
        cvt_fp16<<<(nw + 255) / 256, 256>>>((const float4*)Wk, (__half2*)pwk, nw);
        cvt_fp16<<<(nw + 255) / 256, 256>>>((const float4*)Wv, (__half2*)pwv, nw);
        int no = COUT * COUT / 4;
        cvt_fp16<<<(no + 255) / 256, 256>>>((const float4*)Wo, (__half2*)pwo, no);
    }
    tr_cvt16<<<dim3(CIN / 32, NPIX / 32, BATCH), dim3(32, 8)>>>(x, pxt, CIN, NPIX);

    sparsify_topk<<<256, 256>>>(coeff);
    build_csc<<<1, 256>>>();

    const int SM = 61440;
    dim3 gconv(2, 16, BATCH);
    hgemm<<<gconv, 256, SM>>>(pwq, pxt, pq, CIN, CIN, CIN, 0, bq, scale);
    hgemm<<<gconv, 256, SM>>>(pwk, pxt, pk, CIN, CIN, CIN, 0, bk, scale);
    hgemm<<<gconv, 256, SM>>>(pwv, pxt, pv, CIN, CIN, CIN, 1, bv, scale);

    hgemm<<<dim3(2, 2, BATCH * HEADS), 256, SM>>>(pq, pk, pattn, 256, 2048, 2048, 3, bq, scale);
    mix_softmax<<<BATCH * HEADS * NPIX / 8, 256>>>();
    hgemm<<<dim3(2, 2, BATCH * HEADS), 256, SM>>>(pv, psa, paot, 256, 256, 256, 4, bq, scale);

    hgemm<<<gconv, 256, SM>>>(pwo, paot, out, COUT, COUT, COUT, 2, bo, scale);
}